// round 15
// baseline (speedup 1.0000x reference)
#include <cuda_runtime.h>
#include <cuda_bf16.h>
#include <cstdint>

#define BB 4
#define LL 1024
#define DD 1024
#define HH 16
#define DK 64
#define ML (BB*LL)          // 4096 rows
#define EPS 1e-5f
#define NEG (-1e9f)

// ---------------------------------------------------------------------------
// Static scratch
// ---------------------------------------------------------------------------
__device__ __align__(16) __nv_bfloat16 g_qh_hi[ML*DD];
__device__ __align__(16) __nv_bfloat16 g_qh_lo[ML*DD];
__device__ __align__(16) __nv_bfloat16 g_kh_hi[ML*DD];
__device__ __align__(16) __nv_bfloat16 g_kh_lo[ML*DD];
__device__ __align__(16) float g_vh[ML*DD];
__device__ __align__(16) float g_av[ML*DD];
__device__ __align__(16) float g_tmp[ML*DD];

// ---------------------------------------------------------------------------
// Helpers
// ---------------------------------------------------------------------------
__device__ __forceinline__ uint32_t smem_u32(const void* p) {
    uint32_t a;
    asm("{ .reg .u64 t; cvta.to.shared.u64 t, %1; cvt.u32.u64 %0, t; }" : "=r"(a) : "l"(p));
    return a;
}

__device__ __forceinline__ void split2(float a, float b, uint32_t& ph, uint32_t& pl) {
    __nv_bfloat16 ha = __float2bfloat16(a), hb = __float2bfloat16(b);
    float ra = a - __bfloat162float(ha), rb = b - __bfloat162float(hb);
    __nv_bfloat16 la = __float2bfloat16(ra), lb = __float2bfloat16(rb);
    ph = ((uint32_t)__bfloat16_as_ushort(hb) << 16) | __bfloat16_as_ushort(ha);
    pl = ((uint32_t)__bfloat16_as_ushort(lb) << 16) | __bfloat16_as_ushort(la);
}

__device__ __forceinline__ void ldsm_x4(uint32_t* r, uint32_t addr) {
    asm volatile("ldmatrix.sync.aligned.m8n8.x4.shared.b16 {%0,%1,%2,%3}, [%4];"
        : "=r"(r[0]), "=r"(r[1]), "=r"(r[2]), "=r"(r[3]) : "r"(addr));
}
__device__ __forceinline__ void ldsm_x2_trans(uint32_t* r, uint32_t addr) {
    asm volatile("ldmatrix.sync.aligned.m8n8.x2.trans.shared.b16 {%0,%1}, [%2];"
        : "=r"(r[0]), "=r"(r[1]) : "r"(addr));
}
__device__ __forceinline__ void ldsm_x2(uint32_t* r, uint32_t addr) {
    asm volatile("ldmatrix.sync.aligned.m8n8.x2.shared.b16 {%0,%1}, [%2];"
        : "=r"(r[0]), "=r"(r[1]) : "r"(addr));
}

__device__ __forceinline__ void mma16816(float* c, const uint32_t* a, const uint32_t* b) {
    asm volatile(
        "mma.sync.aligned.m16n8k16.row.col.f32.bf16.bf16.f32 "
        "{%0,%1,%2,%3}, {%4,%5,%6,%7}, {%8,%9}, {%10,%11,%12,%13};"
        : "=f"(c[0]), "=f"(c[1]), "=f"(c[2]), "=f"(c[3])
        : "r"(a[0]), "r"(a[1]), "r"(a[2]), "r"(a[3]), "r"(b[0]), "r"(b[1]),
          "f"(c[0]), "f"(c[1]), "f"(c[2]), "f"(c[3]));
}

// ---------------------------------------------------------------------------
// Tensor-core dense GEMM: C[M,N] = A[M,K] @ W[K,N] + bias, fp32 inputs,
// on-the-fly bf16 hi/lo split, 3-MMA fp32 emulation (m16n8k16).
// CTA 128x128, BK=32, 8 warps (warp tile 64x32), double-buffered smem.
// OUT_SPLIT=0: fp32 C.  OUT_SPLIT=1: bf16 hi/lo C.
// smem elems/stage: A 128x40 (hi+lo) + B 32x136 (hi+lo) = 18944; x2 stages.
// ---------------------------------------------------------------------------
#define GA_STRIDE 40
#define GB_STRIDE 136
#define G_STAGE   18944

template<int OUT_SPLIT>
__global__ __launch_bounds__(256) void gemm_tc(
    const float* __restrict__ A, const float* __restrict__ W,
    const float* __restrict__ bias, float* __restrict__ C,
    __nv_bfloat16* __restrict__ Chi, __nv_bfloat16* __restrict__ Clo,
    int M, int N, int K)
{
    extern __shared__ char smraw[];
    __nv_bfloat16* sm = (__nv_bfloat16*)smraw;
    // per-stage offsets (elems): Ah 0, Al 5120, Bh 10240, Bl 14592

    const int tid  = threadIdx.x;
    const int lane = tid & 31, wid = tid >> 5;
    const int wm = (wid & 1) * 64, wn = (wid >> 1) * 32;
    const int cRow = blockIdx.y, cCol = blockIdx.x;

    const float* Ap = A + (size_t)cRow * 128 * K;
    const float* Wp = W + (size_t)cCol * 128;

    const int arow = tid >> 3, acol = (tid & 7) * 4;   // A: rows arow + p*32
    const int brow = tid >> 5, bcol = (tid & 31) * 4;  // W: rows brow + p*8

    float acc[4][4][4] = {};

    // --- stage 0 direct load ---
    {
        __nv_bfloat16* dAh = sm;
        __nv_bfloat16* dAl = sm + 5120;
        __nv_bfloat16* dBh = sm + 10240;
        __nv_bfloat16* dBl = sm + 14592;
        #pragma unroll
        for (int p = 0; p < 4; p++) {
            int r = arow + p * 32;
            float4 va = *(const float4*)(Ap + (size_t)r * K + acol);
            uint32_t h0, l0, h1, l1;
            split2(va.x, va.y, h0, l0); split2(va.z, va.w, h1, l1);
            *(uint2*)(dAh + r * GA_STRIDE + acol) = make_uint2(h0, h1);
            *(uint2*)(dAl + r * GA_STRIDE + acol) = make_uint2(l0, l1);

            int rw = brow + p * 8;
            float4 vw = *(const float4*)(Wp + (size_t)rw * N + bcol);
            split2(vw.x, vw.y, h0, l0); split2(vw.z, vw.w, h1, l1);
            *(uint2*)(dBh + rw * GB_STRIDE + bcol) = make_uint2(h0, h1);
            *(uint2*)(dBl + rw * GB_STRIDE + bcol) = make_uint2(l0, l1);
        }
    }
    __syncthreads();

    for (int kt = 0; kt < K; kt += 32) {
        const int cur = (kt >> 5) & 1;
        const bool has_next = (kt + 32) < K;
        float4 pa[4], pw[4];
        if (has_next) {
            #pragma unroll
            for (int p = 0; p < 4; p++) {
                pa[p] = *(const float4*)(Ap + (size_t)(arow + p * 32) * K + kt + 32 + acol);
                pw[p] = *(const float4*)(Wp + (size_t)(kt + 32 + brow + p * 8) * N + bcol);
            }
        }

        const __nv_bfloat16* cAh = sm + cur * G_STAGE;
        const __nv_bfloat16* cAl = cAh + 5120;
        const __nv_bfloat16* cBh = cAh + 10240;
        const __nv_bfloat16* cBl = cAh + 14592;

        #pragma unroll
        for (int ks = 0; ks < 32; ks += 16) {
            uint32_t ah[4][4], al[4][4];
            #pragma unroll
            for (int mi = 0; mi < 4; mi++) {
                uint32_t ad = smem_u32(cAh + (wm + mi * 16 + (lane & 15)) * GA_STRIDE
                                       + ks + 8 * (lane >> 4));
                ldsm_x4(ah[mi], ad);
                uint32_t ad2 = smem_u32(cAl + (wm + mi * 16 + (lane & 15)) * GA_STRIDE
                                        + ks + 8 * (lane >> 4));
                ldsm_x4(al[mi], ad2);
            }
            #pragma unroll
            for (int ni = 0; ni < 4; ni++) {
                uint32_t bh[2], bl[2];
                uint32_t bd = smem_u32(cBh + (ks + (lane & 15)) * GB_STRIDE + wn + ni * 8);
                ldsm_x2_trans(bh, bd);
                uint32_t bd2 = smem_u32(cBl + (ks + (lane & 15)) * GB_STRIDE + wn + ni * 8);
                ldsm_x2_trans(bl, bd2);
                #pragma unroll
                for (int mi = 0; mi < 4; mi++) {
                    mma16816(acc[mi][ni], ah[mi], bh);
                    mma16816(acc[mi][ni], ah[mi], bl);
                    mma16816(acc[mi][ni], al[mi], bh);
                }
            }
        }

        if (has_next) {
            __nv_bfloat16* dAh = sm + (cur ^ 1) * G_STAGE;
            __nv_bfloat16* dAl = dAh + 5120;
            __nv_bfloat16* dBh = dAh + 10240;
            __nv_bfloat16* dBl = dAh + 14592;
            #pragma unroll
            for (int p = 0; p < 4; p++) {
                uint32_t h0, l0, h1, l1;
                int r = arow + p * 32;
                split2(pa[p].x, pa[p].y, h0, l0); split2(pa[p].z, pa[p].w, h1, l1);
                *(uint2*)(dAh + r * GA_STRIDE + acol) = make_uint2(h0, h1);
                *(uint2*)(dAl + r * GA_STRIDE + acol) = make_uint2(l0, l1);
                int rw = brow + p * 8;
                split2(pw[p].x, pw[p].y, h0, l0); split2(pw[p].z, pw[p].w, h1, l1);
                *(uint2*)(dBh + rw * GB_STRIDE + bcol) = make_uint2(h0, h1);
                *(uint2*)(dBl + rw * GB_STRIDE + bcol) = make_uint2(l0, l1);
            }
            __syncthreads();
        }
    }

    // Epilogue
    #pragma unroll
    for (int mi = 0; mi < 4; mi++) {
        #pragma unroll
        for (int ni = 0; ni < 4; ni++) {
            const int r0 = cRow * 128 + wm + mi * 16 + (lane >> 2);
            const int c0 = cCol * 128 + wn + ni * 8 + (lane & 3) * 2;
            const float b0 = bias[c0], b1 = bias[c0 + 1];
            float v0 = acc[mi][ni][0] + b0, v1 = acc[mi][ni][1] + b1;
            float v2 = acc[mi][ni][2] + b0, v3 = acc[mi][ni][3] + b1;
            if (OUT_SPLIT == 0) {
                *(float2*)(C + (size_t)r0 * N + c0)       = make_float2(v0, v1);
                *(float2*)(C + (size_t)(r0 + 8) * N + c0) = make_float2(v2, v3);
            } else {
                uint32_t h, l;
                split2(v0, v1, h, l);
                *(uint32_t*)(Chi + (size_t)r0 * N + c0) = h;
                *(uint32_t*)(Clo + (size_t)r0 * N + c0) = l;
                split2(v2, v3, h, l);
                *(uint32_t*)(Chi + (size_t)(r0 + 8) * N + c0) = h;
                *(uint32_t*)(Clo + (size_t)(r0 + 8) * N + c0) = l;
            }
        }
    }
}

// ---------------------------------------------------------------------------
// Attention scores via mma.sync: S = (Q_bh @ K_bh^T) / 8, hi/lo 3-MMA.
// Q,K pre-split bf16 (strided ld=DD). Single-shot K=64.
// smem: Qh[128][72], Ql, Kh[128][72], Kl = 73728 B. grid (8,8,64), 256 thr.
// ---------------------------------------------------------------------------
#define S_STRIDE 72

__global__ __launch_bounds__(256) void scores_tc(
    const __nv_bfloat16* __restrict__ qhi, const __nv_bfloat16* __restrict__ qlo,
    const __nv_bfloat16* __restrict__ khi, const __nv_bfloat16* __restrict__ klo,
    float* __restrict__ attn)
{
    extern __shared__ char smraw[];
    __nv_bfloat16* sQh = (__nv_bfloat16*)smraw;
    __nv_bfloat16* sQl = sQh + 9216;
    __nv_bfloat16* sKh = sQh + 18432;
    __nv_bfloat16* sKl = sQh + 27648;

    const int tid  = threadIdx.x;
    const int lane = tid & 31, wid = tid >> 5;
    const int wm = (wid & 1) * 64, wn = (wid >> 1) * 32;
    const int hh = blockIdx.z & 15, b = blockIdx.z >> 4;
    const int qt = blockIdx.y, ktile = blockIdx.x;

    const size_t qrow0 = (size_t)b * LL + qt * 128;
    const size_t krow0 = (size_t)b * LL + ktile * 128;
    const int colh = hh * DK;

    // Stage tiles: row = tid>>1, half = tid&1 -> 4 uint4 each matrix
    {
        const int r  = tid >> 1;
        const int c0 = (tid & 1) * 32;
        const __nv_bfloat16* gq_h = qhi + (qrow0 + r) * DD + colh + c0;
        const __nv_bfloat16* gq_l = qlo + (qrow0 + r) * DD + colh + c0;
        const __nv_bfloat16* gk_h = khi + (krow0 + r) * DD + colh + c0;
        const __nv_bfloat16* gk_l = klo + (krow0 + r) * DD + colh + c0;
        #pragma unroll
        for (int i = 0; i < 4; i++) {
            *(uint4*)(sQh + r * S_STRIDE + c0 + i * 8) = *(const uint4*)(gq_h + i * 8);
            *(uint4*)(sQl + r * S_STRIDE + c0 + i * 8) = *(const uint4*)(gq_l + i * 8);
            *(uint4*)(sKh + r * S_STRIDE + c0 + i * 8) = *(const uint4*)(gk_h + i * 8);
            *(uint4*)(sKl + r * S_STRIDE + c0 + i * 8) = *(const uint4*)(gk_l + i * 8);
        }
    }
    __syncthreads();

    float acc[4][4][4] = {};

    #pragma unroll
    for (int ks = 0; ks < 64; ks += 16) {
        uint32_t ah[4][4], al[4][4];
        #pragma unroll
        for (int mi = 0; mi < 4; mi++) {
            uint32_t ad = smem_u32(sQh + (wm + mi * 16 + (lane & 15)) * S_STRIDE
                                   + ks + 8 * (lane >> 4));
            ldsm_x4(ah[mi], ad);
            uint32_t ad2 = smem_u32(sQl + (wm + mi * 16 + (lane & 15)) * S_STRIDE
                                    + ks + 8 * (lane >> 4));
            ldsm_x4(al[mi], ad2);
        }
        #pragma unroll
        for (int ni = 0; ni < 4; ni++) {
            // B col-major frag from token-major K tile: non-trans ldmatrix
            const int nrow = wn + ni * 8 + (lane & 7);
            const int kblk = ks + 8 * ((lane >> 3) & 1);
            uint32_t bh[2], bl[2];
            ldsm_x2(bh, smem_u32(sKh + nrow * S_STRIDE + kblk));
            ldsm_x2(bl, smem_u32(sKl + nrow * S_STRIDE + kblk));
            #pragma unroll
            for (int mi = 0; mi < 4; mi++) {
                mma16816(acc[mi][ni], ah[mi], bh);
                mma16816(acc[mi][ni], ah[mi], bl);
                mma16816(acc[mi][ni], al[mi], bh);
            }
        }
    }

    float* Cp = attn + ((size_t)(hh * BB + b) * LL) * LL;
    #pragma unroll
    for (int mi = 0; mi < 4; mi++) {
        #pragma unroll
        for (int ni = 0; ni < 4; ni++) {
            const int r0 = qt * 128 + wm + mi * 16 + (lane >> 2);
            const int c0 = ktile * 128 + wn + ni * 8 + (lane & 3) * 2;
            *(float2*)(Cp + (size_t)r0 * LL + c0) =
                make_float2(acc[mi][ni][0] * 0.125f, acc[mi][ni][1] * 0.125f);
            *(float2*)(Cp + (size_t)(r0 + 8) * LL + c0) =
                make_float2(acc[mi][ni][2] * 0.125f, acc[mi][ni][3] * 0.125f);
        }
    }
}

// ---------------------------------------------------------------------------
// Softmax
// ---------------------------------------------------------------------------
__device__ __forceinline__ float warpMax(float v) {
    #pragma unroll
    for (int o = 16; o; o >>= 1) v = fmaxf(v, __shfl_xor_sync(0xffffffffu, v, o));
    return v;
}
__device__ __forceinline__ float warpSum(float v) {
    #pragma unroll
    for (int o = 16; o; o >>= 1) v += __shfl_xor_sync(0xffffffffu, v, o);
    return v;
}

__global__ __launch_bounds__(256) void softmax_rows(
    float* __restrict__ attn, const uint8_t* __restrict__ mask)
{
    const int row = blockIdx.x;
    const int qi  = row & 1023;
    const int b   = (row >> 10) & (BB - 1);
    float* rp = attn + (size_t)row * LL;
    const uint8_t* mp = mask + ((size_t)b * LL + qi) * LL;

    const int t = threadIdx.x;
    __shared__ float red[8];

    float v[4];
    #pragma unroll
    for (int i = 0; i < 4; i++) {
        int idx = t + i * 256;
        float s = rp[idx];
        v[i] = mp[idx] ? NEG : s;
    }
    float m = fmaxf(fmaxf(v[0], v[1]), fmaxf(v[2], v[3]));
    m = warpMax(m);
    if ((t & 31) == 0) red[t >> 5] = m;
    __syncthreads();
    float rowmax = red[0];
    #pragma unroll
    for (int i = 1; i < 8; i++) rowmax = fmaxf(rowmax, red[i]);
    __syncthreads();

    float s = 0.f;
    #pragma unroll
    for (int i = 0; i < 4; i++) { v[i] = expf(v[i] - rowmax); s += v[i]; }
    s = warpSum(s);
    if ((t & 31) == 0) red[t >> 5] = s;
    __syncthreads();
    float rowsum = 0.f;
    #pragma unroll
    for (int i = 0; i < 8; i++) rowsum += red[i];
    float inv = 1.f / rowsum;
    #pragma unroll
    for (int i = 0; i < 4; i++) rp[t + i * 256] = v[i] * inv;
}

// ---------------------------------------------------------------------------
// PV: per head C[1024,64] = P @ V_bh (fp32 FFMA, double-buffered)
// ---------------------------------------------------------------------------
__global__ __launch_bounds__(256) void attn_pv(
    const float* __restrict__ attn, const float* __restrict__ vh,
    float* __restrict__ outAV)
{
    __shared__ float As[2][16][128];
    __shared__ float Bs[2][16][64];

    const int tid  = threadIdx.x;
    const int cRow = blockIdx.x;
    const int bh   = blockIdx.z;
    const int b    = bh / HH;
    const int h    = bh % HH;

    const float* Ap = attn + ((size_t)(h * BB + b) * LL) * LL + (size_t)cRow * 128 * LL;
    const float* Vp = vh + (size_t)b * LL * DD + (size_t)h * DK;
    float* Cp = outAV + (size_t)b * LL * DD + (size_t)h * DK + (size_t)cRow * 128 * DD;

    const int aRow = tid >> 2;
    const int aCol = (tid & 3) * 4;
    const int bRow = tid >> 4;
    const int bCol = (tid & 15) * 4;
    const int tRow = (tid >> 4) * 8;
    const int tCol = (tid & 15) * 4;

    float acc[8][4] = {};

    #pragma unroll
    for (int rr = 0; rr < 128; rr += 64) {
        float4 av = *reinterpret_cast<const float4*>(Ap + (size_t)(aRow + rr) * LL + aCol);
        As[0][aCol + 0][aRow + rr] = av.x;
        As[0][aCol + 1][aRow + rr] = av.y;
        As[0][aCol + 2][aRow + rr] = av.z;
        As[0][aCol + 3][aRow + rr] = av.w;
    }
    *reinterpret_cast<float4*>(&Bs[0][bRow][bCol]) =
        *reinterpret_cast<const float4*>(Vp + (size_t)bRow * DD + bCol);
    __syncthreads();

    int cur = 0;
    for (int kt = 0; kt < LL; kt += 16) {
        const bool has_next = (kt + 16) < LL;
        float4 an0, an1, bn;
        if (has_next) {
            an0 = *reinterpret_cast<const float4*>(Ap + (size_t)(aRow +  0) * LL + kt + 16 + aCol);
            an1 = *reinterpret_cast<const float4*>(Ap + (size_t)(aRow + 64) * LL + kt + 16 + aCol);
            bn  = *reinterpret_cast<const float4*>(Vp + (size_t)(kt + 16 + bRow) * DD + bCol);
        }

        #pragma unroll
        for (int k = 0; k < 16; k++) {
            float rm[8], rn[4];
            *reinterpret_cast<float4*>(&rm[0]) = *reinterpret_cast<const float4*>(&As[cur][k][tRow]);
            *reinterpret_cast<float4*>(&rm[4]) = *reinterpret_cast<const float4*>(&As[cur][k][tRow + 4]);
            *reinterpret_cast<float4*>(&rn[0]) = *reinterpret_cast<const float4*>(&Bs[cur][k][tCol]);
            #pragma unroll
            for (int i = 0; i < 8; i++)
                #pragma unroll
                for (int j = 0; j < 4; j++)
                    acc[i][j] = fmaf(rm[i], rn[j], acc[i][j]);
        }

        if (has_next) {
            const int nxt = cur ^ 1;
            As[nxt][aCol + 0][aRow +  0] = an0.x;
            As[nxt][aCol + 1][aRow +  0] = an0.y;
            As[nxt][aCol + 2][aRow +  0] = an0.z;
            As[nxt][aCol + 3][aRow +  0] = an0.w;
            As[nxt][aCol + 0][aRow + 64] = an1.x;
            As[nxt][aCol + 1][aRow + 64] = an1.y;
            As[nxt][aCol + 2][aRow + 64] = an1.z;
            As[nxt][aCol + 3][aRow + 64] = an1.w;
            *reinterpret_cast<float4*>(&Bs[nxt][bRow][bCol]) = bn;
            __syncthreads();
            cur = nxt;
        }
    }

    #pragma unroll
    for (int i = 0; i < 8; i++) {
        float4 o;
        o.x = acc[i][0]; o.y = acc[i][1]; o.z = acc[i][2]; o.w = acc[i][3];
        *reinterpret_cast<float4*>(Cp + (size_t)(tRow + i) * DD + tCol) = o;
    }
}

// ---------------------------------------------------------------------------
// Residual + LayerNorm
// ---------------------------------------------------------------------------
__global__ __launch_bounds__(256) void add_layernorm(
    const float* __restrict__ xin, const float* __restrict__ resid,
    const float* __restrict__ gamma, const float* __restrict__ beta,
    float* __restrict__ y)
{
    const int row = blockIdx.x;
    const int t = threadIdx.x;
    __shared__ float rs[8], rss[8];

    float4 a = reinterpret_cast<const float4*>(xin + (size_t)row * DD)[t];
    float4 r = reinterpret_cast<const float4*>(resid + (size_t)row * DD)[t];
    a.x += r.x; a.y += r.y; a.z += r.z; a.w += r.w;

    float s  = a.x + a.y + a.z + a.w;
    float ss = a.x * a.x + a.y * a.y + a.z * a.z + a.w * a.w;
    s = warpSum(s);
    ss = warpSum(ss);
    if ((t & 31) == 0) { rs[t >> 5] = s; rss[t >> 5] = ss; }
    __syncthreads();
    float tot = 0.f, tot2 = 0.f;
    #pragma unroll
    for (int i = 0; i < 8; i++) { tot += rs[i]; tot2 += rss[i]; }
    float mu   = tot * (1.0f / DD);
    float var  = tot2 * (1.0f / DD) - mu * mu;
    float rstd = rsqrtf(var + EPS);

    float4 g  = reinterpret_cast<const float4*>(gamma)[t];
    float4 be = reinterpret_cast<const float4*>(beta)[t];
    float4 o;
    o.x = (a.x - mu) * rstd * g.x + be.x;
    o.y = (a.y - mu) * rstd * g.y + be.y;
    o.z = (a.z - mu) * rstd * g.z + be.z;
    o.w = (a.w - mu) * rstd * g.w + be.w;
    reinterpret_cast<float4*>(y + (size_t)row * DD)[t] = o;
}

// ---------------------------------------------------------------------------
extern "C" void kernel_launch(void* const* d_in, const int* in_sizes, int n_in,
                              void* d_out, int out_size)
{
    const float*   q     = (const float*)d_in[0];
    const float*   k     = (const float*)d_in[1];
    const float*   v     = (const float*)d_in[2];
    const uint8_t* mask  = (const uint8_t*)d_in[3];
    const float*   wq    = (const float*)d_in[4];
    const float*   bq    = (const float*)d_in[5];
    const float*   wk    = (const float*)d_in[6];
    const float*   bk    = (const float*)d_in[7];
    const float*   wv    = (const float*)d_in[8];
    const float*   bv    = (const float*)d_in[9];
    const float*   wfc   = (const float*)d_in[10];
    const float*   bfc   = (const float*)d_in[11];
    const float*   gamma = (const float*)d_in[12];
    const float*   beta  = (const float*)d_in[13];

    float* out  = (float*)d_out;
    float* y    = out;
    float* attn = out + (size_t)BB * LL * DD;

    void *qhh, *qhl, *khh, *khl, *pvh, *pav, *ptmp;
    cudaGetSymbolAddress(&qhh, g_qh_hi);
    cudaGetSymbolAddress(&qhl, g_qh_lo);
    cudaGetSymbolAddress(&khh, g_kh_hi);
    cudaGetSymbolAddress(&khl, g_kh_lo);
    cudaGetSymbolAddress(&pvh, g_vh);
    cudaGetSymbolAddress(&pav, g_av);
    cudaGetSymbolAddress(&ptmp, g_tmp);

    const int G_SMEM = 2 * G_STAGE * 2;   // 75776 bytes
    const int S_SMEM = 4 * 9216 * 2;      // 73728 bytes
    cudaFuncSetAttribute(gemm_tc<0>, cudaFuncAttributeMaxDynamicSharedMemorySize, G_SMEM);
    cudaFuncSetAttribute(gemm_tc<1>, cudaFuncAttributeMaxDynamicSharedMemorySize, G_SMEM);
    cudaFuncSetAttribute(scores_tc, cudaFuncAttributeMaxDynamicSharedMemorySize, S_SMEM);

    dim3 gProj(DD / 128, ML / 128);          // (8, 32)
    gemm_tc<1><<<gProj, 256, G_SMEM>>>(q, wq, bq, nullptr,
        (__nv_bfloat16*)qhh, (__nv_bfloat16*)qhl, ML, DD, DD);
    gemm_tc<1><<<gProj, 256, G_SMEM>>>(k, wk, bk, nullptr,
        (__nv_bfloat16*)khh, (__nv_bfloat16*)khl, ML, DD, DD);
    gemm_tc<0><<<gProj, 256, G_SMEM>>>(v, wv, bv, (float*)pvh,
        nullptr, nullptr, ML, DD, DD);

    dim3 gScores(LL / 128, LL / 128, BB * HH);   // (8, 8, 64)
    scores_tc<<<gScores, 256, S_SMEM>>>(
        (const __nv_bfloat16*)qhh, (const __nv_bfloat16*)qhl,
        (const __nv_bfloat16*)khh, (const __nv_bfloat16*)khl, attn);

    softmax_rows<<<BB * HH * LL, 256>>>(attn, mask);

    dim3 gPV(LL / 128, 1, BB * HH);              // (8, 1, 64)
    attn_pv<<<gPV, 256>>>(attn, (const float*)pvh, (float*)pav);

    gemm_tc<0><<<gProj, 256, G_SMEM>>>((const float*)pav, wfc, bfc, (float*)ptmp,
        nullptr, nullptr, ML, DD, DD);

    add_layernorm<<<ML, 256>>>((const float*)ptmp, q, gamma, beta, y);
}

// round 16
// speedup vs baseline: 1.0010x; 1.0010x over previous
#include <cuda_runtime.h>
#include <cuda_bf16.h>
#include <cstdint>

#define BB 4
#define LL 1024
#define DD 1024
#define HH 16
#define DK 64
#define ML (BB*LL)          // 4096 rows
#define EPS 1e-5f
#define NEG (-1e9f)

// ---------------------------------------------------------------------------
// Static scratch
// ---------------------------------------------------------------------------
__device__ __align__(16) __nv_bfloat16 g_qh_hi[ML*DD];
__device__ __align__(16) __nv_bfloat16 g_qh_lo[ML*DD];
__device__ __align__(16) __nv_bfloat16 g_kh_hi[ML*DD];
__device__ __align__(16) __nv_bfloat16 g_kh_lo[ML*DD];
__device__ __align__(16) float g_vh[ML*DD];
__device__ __align__(16) float g_av[ML*DD];
__device__ __align__(16) float g_tmp[ML*DD];

// ---------------------------------------------------------------------------
// Helpers
// ---------------------------------------------------------------------------
__device__ __forceinline__ uint32_t smem_u32(const void* p) {
    uint32_t a;
    asm("{ .reg .u64 t; cvta.to.shared.u64 t, %1; cvt.u32.u64 %0, t; }" : "=r"(a) : "l"(p));
    return a;
}

__device__ __forceinline__ void split2(float a, float b, uint32_t& ph, uint32_t& pl) {
    __nv_bfloat16 ha = __float2bfloat16(a), hb = __float2bfloat16(b);
    float ra = a - __bfloat162float(ha), rb = b - __bfloat162float(hb);
    __nv_bfloat16 la = __float2bfloat16(ra), lb = __float2bfloat16(rb);
    ph = ((uint32_t)__bfloat16_as_ushort(hb) << 16) | __bfloat16_as_ushort(ha);
    pl = ((uint32_t)__bfloat16_as_ushort(lb) << 16) | __bfloat16_as_ushort(la);
}

__device__ __forceinline__ void ldsm_x4(uint32_t* r, uint32_t addr) {
    asm volatile("ldmatrix.sync.aligned.m8n8.x4.shared.b16 {%0,%1,%2,%3}, [%4];"
        : "=r"(r[0]), "=r"(r[1]), "=r"(r[2]), "=r"(r[3]) : "r"(addr));
}
__device__ __forceinline__ void ldsm_x2_trans(uint32_t* r, uint32_t addr) {
    asm volatile("ldmatrix.sync.aligned.m8n8.x2.trans.shared.b16 {%0,%1}, [%2];"
        : "=r"(r[0]), "=r"(r[1]) : "r"(addr));
}
__device__ __forceinline__ void ldsm_x2(uint32_t* r, uint32_t addr) {
    asm volatile("ldmatrix.sync.aligned.m8n8.x2.shared.b16 {%0,%1}, [%2];"
        : "=r"(r[0]), "=r"(r[1]) : "r"(addr));
}

__device__ __forceinline__ void mma16816(float* c, const uint32_t* a, const uint32_t* b) {
    asm volatile(
        "mma.sync.aligned.m16n8k16.row.col.f32.bf16.bf16.f32 "
        "{%0,%1,%2,%3}, {%4,%5,%6,%7}, {%8,%9}, {%10,%11,%12,%13};"
        : "=f"(c[0]), "=f"(c[1]), "=f"(c[2]), "=f"(c[3])
        : "r"(a[0]), "r"(a[1]), "r"(a[2]), "r"(a[3]), "r"(b[0]), "r"(b[1]),
          "f"(c[0]), "f"(c[1]), "f"(c[2]), "f"(c[3]));
}

// ---------------------------------------------------------------------------
// Tensor-core dense GEMM: C[M,N] = A[M,K] @ W[K,N] + bias, fp32 inputs,
// on-the-fly bf16 hi/lo split, 3-MMA fp32 emulation (m16n8k16).
// CTA 128x128, BK=32, 8 warps (warp tile 64x32), double-buffered smem.
// OUT_SPLIT=0: fp32 C.  OUT_SPLIT=1: bf16 hi/lo C.
// smem elems/stage: A 128x40 (hi+lo) + B 32x136 (hi+lo) = 18944; x2 stages.
// ---------------------------------------------------------------------------
#define GA_STRIDE 40
#define GB_STRIDE 136
#define G_STAGE   18944

template<int OUT_SPLIT>
__global__ __launch_bounds__(256) void gemm_tc(
    const float* __restrict__ A, const float* __restrict__ W,
    const float* __restrict__ bias, float* __restrict__ C,
    __nv_bfloat16* __restrict__ Chi, __nv_bfloat16* __restrict__ Clo,
    int M, int N, int K)
{
    extern __shared__ char smraw[];
    __nv_bfloat16* sm = (__nv_bfloat16*)smraw;
    // per-stage offsets (elems): Ah 0, Al 5120, Bh 10240, Bl 14592

    const int tid  = threadIdx.x;
    const int lane = tid & 31, wid = tid >> 5;
    const int wm = (wid & 1) * 64, wn = (wid >> 1) * 32;
    const int cRow = blockIdx.y, cCol = blockIdx.x;

    const float* Ap = A + (size_t)cRow * 128 * K;
    const float* Wp = W + (size_t)cCol * 128;

    const int arow = tid >> 3, acol = (tid & 7) * 4;   // A: rows arow + p*32
    const int brow = tid >> 5, bcol = (tid & 31) * 4;  // W: rows brow + p*8

    float acc[4][4][4] = {};

    // --- stage 0 direct load ---
    {
        __nv_bfloat16* dAh = sm;
        __nv_bfloat16* dAl = sm + 5120;
        __nv_bfloat16* dBh = sm + 10240;
        __nv_bfloat16* dBl = sm + 14592;
        #pragma unroll
        for (int p = 0; p < 4; p++) {
            int r = arow + p * 32;
            float4 va = *(const float4*)(Ap + (size_t)r * K + acol);
            uint32_t h0, l0, h1, l1;
            split2(va.x, va.y, h0, l0); split2(va.z, va.w, h1, l1);
            *(uint2*)(dAh + r * GA_STRIDE + acol) = make_uint2(h0, h1);
            *(uint2*)(dAl + r * GA_STRIDE + acol) = make_uint2(l0, l1);

            int rw = brow + p * 8;
            float4 vw = *(const float4*)(Wp + (size_t)rw * N + bcol);
            split2(vw.x, vw.y, h0, l0); split2(vw.z, vw.w, h1, l1);
            *(uint2*)(dBh + rw * GB_STRIDE + bcol) = make_uint2(h0, h1);
            *(uint2*)(dBl + rw * GB_STRIDE + bcol) = make_uint2(l0, l1);
        }
    }
    __syncthreads();

    for (int kt = 0; kt < K; kt += 32) {
        const int cur = (kt >> 5) & 1;
        const bool has_next = (kt + 32) < K;
        float4 pa[4], pw[4];
        if (has_next) {
            #pragma unroll
            for (int p = 0; p < 4; p++) {
                pa[p] = *(const float4*)(Ap + (size_t)(arow + p * 32) * K + kt + 32 + acol);
                pw[p] = *(const float4*)(Wp + (size_t)(kt + 32 + brow + p * 8) * N + bcol);
            }
        }

        const __nv_bfloat16* cAh = sm + cur * G_STAGE;
        const __nv_bfloat16* cAl = cAh + 5120;
        const __nv_bfloat16* cBh = cAh + 10240;
        const __nv_bfloat16* cBl = cAh + 14592;

        #pragma unroll
        for (int ks = 0; ks < 32; ks += 16) {
            uint32_t ah[4][4], al[4][4];
            #pragma unroll
            for (int mi = 0; mi < 4; mi++) {
                uint32_t ad = smem_u32(cAh + (wm + mi * 16 + (lane & 15)) * GA_STRIDE
                                       + ks + 8 * (lane >> 4));
                ldsm_x4(ah[mi], ad);
                uint32_t ad2 = smem_u32(cAl + (wm + mi * 16 + (lane & 15)) * GA_STRIDE
                                        + ks + 8 * (lane >> 4));
                ldsm_x4(al[mi], ad2);
            }
            #pragma unroll
            for (int ni = 0; ni < 4; ni++) {
                uint32_t bh[2], bl[2];
                uint32_t bd = smem_u32(cBh + (ks + (lane & 15)) * GB_STRIDE + wn + ni * 8);
                ldsm_x2_trans(bh, bd);
                uint32_t bd2 = smem_u32(cBl + (ks + (lane & 15)) * GB_STRIDE + wn + ni * 8);
                ldsm_x2_trans(bl, bd2);
                #pragma unroll
                for (int mi = 0; mi < 4; mi++) {
                    mma16816(acc[mi][ni], ah[mi], bh);
                    mma16816(acc[mi][ni], ah[mi], bl);
                    mma16816(acc[mi][ni], al[mi], bh);
                }
            }
        }

        if (has_next) {
            __nv_bfloat16* dAh = sm + (cur ^ 1) * G_STAGE;
            __nv_bfloat16* dAl = dAh + 5120;
            __nv_bfloat16* dBh = dAh + 10240;
            __nv_bfloat16* dBl = dAh + 14592;
            #pragma unroll
            for (int p = 0; p < 4; p++) {
                uint32_t h0, l0, h1, l1;
                int r = arow + p * 32;
                split2(pa[p].x, pa[p].y, h0, l0); split2(pa[p].z, pa[p].w, h1, l1);
                *(uint2*)(dAh + r * GA_STRIDE + acol) = make_uint2(h0, h1);
                *(uint2*)(dAl + r * GA_STRIDE + acol) = make_uint2(l0, l1);
                int rw = brow + p * 8;
                split2(pw[p].x, pw[p].y, h0, l0); split2(pw[p].z, pw[p].w, h1, l1);
                *(uint2*)(dBh + rw * GB_STRIDE + bcol) = make_uint2(h0, h1);
                *(uint2*)(dBl + rw * GB_STRIDE + bcol) = make_uint2(l0, l1);
            }
            __syncthreads();
        }
    }

    // Epilogue
    #pragma unroll
    for (int mi = 0; mi < 4; mi++) {
        #pragma unroll
        for (int ni = 0; ni < 4; ni++) {
            const int r0 = cRow * 128 + wm + mi * 16 + (lane >> 2);
            const int c0 = cCol * 128 + wn + ni * 8 + (lane & 3) * 2;
            const float b0 = bias[c0], b1 = bias[c0 + 1];
            float v0 = acc[mi][ni][0] + b0, v1 = acc[mi][ni][1] + b1;
            float v2 = acc[mi][ni][2] + b0, v3 = acc[mi][ni][3] + b1;
            if (OUT_SPLIT == 0) {
                *(float2*)(C + (size_t)r0 * N + c0)       = make_float2(v0, v1);
                *(float2*)(C + (size_t)(r0 + 8) * N + c0) = make_float2(v2, v3);
            } else {
                uint32_t h, l;
                split2(v0, v1, h, l);
                *(uint32_t*)(Chi + (size_t)r0 * N + c0) = h;
                *(uint32_t*)(Clo + (size_t)r0 * N + c0) = l;
                split2(v2, v3, h, l);
                *(uint32_t*)(Chi + (size_t)(r0 + 8) * N + c0) = h;
                *(uint32_t*)(Clo + (size_t)(r0 + 8) * N + c0) = l;
            }
        }
    }
}

// ---------------------------------------------------------------------------
// Attention scores via mma.sync: S = (Q_bh @ K_bh^T) / 8, hi/lo 3-MMA.
// Q,K pre-split bf16 (strided ld=DD). Single-shot K=64.
// smem: Qh[128][72], Ql, Kh[128][72], Kl = 73728 B. grid (8,8,64), 256 thr.
// ---------------------------------------------------------------------------
#define S_STRIDE 72

__global__ __launch_bounds__(256) void scores_tc(
    const __nv_bfloat16* __restrict__ qhi, const __nv_bfloat16* __restrict__ qlo,
    const __nv_bfloat16* __restrict__ khi, const __nv_bfloat16* __restrict__ klo,
    float* __restrict__ attn)
{
    extern __shared__ char smraw[];
    __nv_bfloat16* sQh = (__nv_bfloat16*)smraw;
    __nv_bfloat16* sQl = sQh + 9216;
    __nv_bfloat16* sKh = sQh + 18432;
    __nv_bfloat16* sKl = sQh + 27648;

    const int tid  = threadIdx.x;
    const int lane = tid & 31, wid = tid >> 5;
    const int wm = (wid & 1) * 64, wn = (wid >> 1) * 32;
    const int hh = blockIdx.z & 15, b = blockIdx.z >> 4;
    const int qt = blockIdx.y, ktile = blockIdx.x;

    const size_t qrow0 = (size_t)b * LL + qt * 128;
    const size_t krow0 = (size_t)b * LL + ktile * 128;
    const int colh = hh * DK;

    // Stage tiles: row = tid>>1, half = tid&1 -> 4 uint4 each matrix
    {
        const int r  = tid >> 1;
        const int c0 = (tid & 1) * 32;
        const __nv_bfloat16* gq_h = qhi + (qrow0 + r) * DD + colh + c0;
        const __nv_bfloat16* gq_l = qlo + (qrow0 + r) * DD + colh + c0;
        const __nv_bfloat16* gk_h = khi + (krow0 + r) * DD + colh + c0;
        const __nv_bfloat16* gk_l = klo + (krow0 + r) * DD + colh + c0;
        #pragma unroll
        for (int i = 0; i < 4; i++) {
            *(uint4*)(sQh + r * S_STRIDE + c0 + i * 8) = *(const uint4*)(gq_h + i * 8);
            *(uint4*)(sQl + r * S_STRIDE + c0 + i * 8) = *(const uint4*)(gq_l + i * 8);
            *(uint4*)(sKh + r * S_STRIDE + c0 + i * 8) = *(const uint4*)(gk_h + i * 8);
            *(uint4*)(sKl + r * S_STRIDE + c0 + i * 8) = *(const uint4*)(gk_l + i * 8);
        }
    }
    __syncthreads();

    float acc[4][4][4] = {};

    #pragma unroll
    for (int ks = 0; ks < 64; ks += 16) {
        uint32_t ah[4][4], al[4][4];
        #pragma unroll
        for (int mi = 0; mi < 4; mi++) {
            uint32_t ad = smem_u32(sQh + (wm + mi * 16 + (lane & 15)) * S_STRIDE
                                   + ks + 8 * (lane >> 4));
            ldsm_x4(ah[mi], ad);
            uint32_t ad2 = smem_u32(sQl + (wm + mi * 16 + (lane & 15)) * S_STRIDE
                                    + ks + 8 * (lane >> 4));
            ldsm_x4(al[mi], ad2);
        }
        #pragma unroll
        for (int ni = 0; ni < 4; ni++) {
            // B col-major frag from token-major K tile: non-trans ldmatrix
            const int nrow = wn + ni * 8 + (lane & 7);
            const int kblk = ks + 8 * ((lane >> 3) & 1);
            uint32_t bh[2], bl[2];
            ldsm_x2(bh, smem_u32(sKh + nrow * S_STRIDE + kblk));
            ldsm_x2(bl, smem_u32(sKl + nrow * S_STRIDE + kblk));
            #pragma unroll
            for (int mi = 0; mi < 4; mi++) {
                mma16816(acc[mi][ni], ah[mi], bh);
                mma16816(acc[mi][ni], ah[mi], bl);
                mma16816(acc[mi][ni], al[mi], bh);
            }
        }
    }

    float* Cp = attn + ((size_t)(hh * BB + b) * LL) * LL;
    #pragma unroll
    for (int mi = 0; mi < 4; mi++) {
        #pragma unroll
        for (int ni = 0; ni < 4; ni++) {
            const int r0 = qt * 128 + wm + mi * 16 + (lane >> 2);
            const int c0 = ktile * 128 + wn + ni * 8 + (lane & 3) * 2;
            *(float2*)(Cp + (size_t)r0 * LL + c0) =
                make_float2(acc[mi][ni][0] * 0.125f, acc[mi][ni][1] * 0.125f);
            *(float2*)(Cp + (size_t)(r0 + 8) * LL + c0) =
                make_float2(acc[mi][ni][2] * 0.125f, acc[mi][ni][3] * 0.125f);
        }
    }
}

// ---------------------------------------------------------------------------
// Softmax
// ---------------------------------------------------------------------------
__device__ __forceinline__ float warpMax(float v) {
    #pragma unroll
    for (int o = 16; o; o >>= 1) v = fmaxf(v, __shfl_xor_sync(0xffffffffu, v, o));
    return v;
}
__device__ __forceinline__ float warpSum(float v) {
    #pragma unroll
    for (int o = 16; o; o >>= 1) v += __shfl_xor_sync(0xffffffffu, v, o);
    return v;
}

__global__ __launch_bounds__(256) void softmax_rows(
    float* __restrict__ attn, const uint8_t* __restrict__ mask)
{
    const int row = blockIdx.x;
    const int qi  = row & 1023;
    const int b   = (row >> 10) & (BB - 1);
    float* rp = attn + (size_t)row * LL;
    const uint8_t* mp = mask + ((size_t)b * LL + qi) * LL;

    const int t = threadIdx.x;
    __shared__ float red[8];

    float v[4];
    #pragma unroll
    for (int i = 0; i < 4; i++) {
        int idx = t + i * 256;
        float s = rp[idx];
        v[i] = mp[idx] ? NEG : s;
    }
    float m = fmaxf(fmaxf(v[0], v[1]), fmaxf(v[2], v[3]));
    m = warpMax(m);
    if ((t & 31) == 0) red[t >> 5] = m;
    __syncthreads();
    float rowmax = red[0];
    #pragma unroll
    for (int i = 1; i < 8; i++) rowmax = fmaxf(rowmax, red[i]);
    __syncthreads();

    float s = 0.f;
    #pragma unroll
    for (int i = 0; i < 4; i++) { v[i] = expf(v[i] - rowmax); s += v[i]; }
    s = warpSum(s);
    if ((t & 31) == 0) red[t >> 5] = s;
    __syncthreads();
    float rowsum = 0.f;
    #pragma unroll
    for (int i = 0; i < 8; i++) rowsum += red[i];
    float inv = 1.f / rowsum;
    #pragma unroll
    for (int i = 0; i < 4; i++) rp[t + i * 256] = v[i] * inv;
}

// ---------------------------------------------------------------------------
// PV: per head C[1024,64] = P @ V_bh (fp32 FFMA, double-buffered)
// ---------------------------------------------------------------------------
__global__ __launch_bounds__(256) void attn_pv(
    const float* __restrict__ attn, const float* __restrict__ vh,
    float* __restrict__ outAV)
{
    __shared__ float As[2][16][128];
    __shared__ float Bs[2][16][64];

    const int tid  = threadIdx.x;
    const int cRow = blockIdx.x;
    const int bh   = blockIdx.z;
    const int b    = bh / HH;
    const int h    = bh % HH;

    const float* Ap = attn + ((size_t)(h * BB + b) * LL) * LL + (size_t)cRow * 128 * LL;
    const float* Vp = vh + (size_t)b * LL * DD + (size_t)h * DK;
    float* Cp = outAV + (size_t)b * LL * DD + (size_t)h * DK + (size_t)cRow * 128 * DD;

    const int aRow = tid >> 2;
    const int aCol = (tid & 3) * 4;
    const int bRow = tid >> 4;
    const int bCol = (tid & 15) * 4;
    const int tRow = (tid >> 4) * 8;
    const int tCol = (tid & 15) * 4;

    float acc[8][4] = {};

    #pragma unroll
    for (int rr = 0; rr < 128; rr += 64) {
        float4 av = *reinterpret_cast<const float4*>(Ap + (size_t)(aRow + rr) * LL + aCol);
        As[0][aCol + 0][aRow + rr] = av.x;
        As[0][aCol + 1][aRow + rr] = av.y;
        As[0][aCol + 2][aRow + rr] = av.z;
        As[0][aCol + 3][aRow + rr] = av.w;
    }
    *reinterpret_cast<float4*>(&Bs[0][bRow][bCol]) =
        *reinterpret_cast<const float4*>(Vp + (size_t)bRow * DD + bCol);
    __syncthreads();

    int cur = 0;
    for (int kt = 0; kt < LL; kt += 16) {
        const bool has_next = (kt + 16) < LL;
        float4 an0, an1, bn;
        if (has_next) {
            an0 = *reinterpret_cast<const float4*>(Ap + (size_t)(aRow +  0) * LL + kt + 16 + aCol);
            an1 = *reinterpret_cast<const float4*>(Ap + (size_t)(aRow + 64) * LL + kt + 16 + aCol);
            bn  = *reinterpret_cast<const float4*>(Vp + (size_t)(kt + 16 + bRow) * DD + bCol);
        }

        #pragma unroll
        for (int k = 0; k < 16; k++) {
            float rm[8], rn[4];
            *reinterpret_cast<float4*>(&rm[0]) = *reinterpret_cast<const float4*>(&As[cur][k][tRow]);
            *reinterpret_cast<float4*>(&rm[4]) = *reinterpret_cast<const float4*>(&As[cur][k][tRow + 4]);
            *reinterpret_cast<float4*>(&rn[0]) = *reinterpret_cast<const float4*>(&Bs[cur][k][tCol]);
            #pragma unroll
            for (int i = 0; i < 8; i++)
                #pragma unroll
                for (int j = 0; j < 4; j++)
                    acc[i][j] = fmaf(rm[i], rn[j], acc[i][j]);
        }

        if (has_next) {
            const int nxt = cur ^ 1;
            As[nxt][aCol + 0][aRow +  0] = an0.x;
            As[nxt][aCol + 1][aRow +  0] = an0.y;
            As[nxt][aCol + 2][aRow +  0] = an0.z;
            As[nxt][aCol + 3][aRow +  0] = an0.w;
            As[nxt][aCol + 0][aRow + 64] = an1.x;
            As[nxt][aCol + 1][aRow + 64] = an1.y;
            As[nxt][aCol + 2][aRow + 64] = an1.z;
            As[nxt][aCol + 3][aRow + 64] = an1.w;
            *reinterpret_cast<float4*>(&Bs[nxt][bRow][bCol]) = bn;
            __syncthreads();
            cur = nxt;
        }
    }

    #pragma unroll
    for (int i = 0; i < 8; i++) {
        float4 o;
        o.x = acc[i][0]; o.y = acc[i][1]; o.z = acc[i][2]; o.w = acc[i][3];
        *reinterpret_cast<float4*>(Cp + (size_t)(tRow + i) * DD + tCol) = o;
    }
}

// ---------------------------------------------------------------------------
// Residual + LayerNorm
// ---------------------------------------------------------------------------
__global__ __launch_bounds__(256) void add_layernorm(
    const float* __restrict__ xin, const float* __restrict__ resid,
    const float* __restrict__ gamma, const float* __restrict__ beta,
    float* __restrict__ y)
{
    const int row = blockIdx.x;
    const int t = threadIdx.x;
    __shared__ float rs[8], rss[8];

    float4 a = reinterpret_cast<const float4*>(xin + (size_t)row * DD)[t];
    float4 r = reinterpret_cast<const float4*>(resid + (size_t)row * DD)[t];
    a.x += r.x; a.y += r.y; a.z += r.z; a.w += r.w;

    float s  = a.x + a.y + a.z + a.w;
    float ss = a.x * a.x + a.y * a.y + a.z * a.z + a.w * a.w;
    s = warpSum(s);
    ss = warpSum(ss);
    if ((t & 31) == 0) { rs[t >> 5] = s; rss[t >> 5] = ss; }
    __syncthreads();
    float tot = 0.f, tot2 = 0.f;
    #pragma unroll
    for (int i = 0; i < 8; i++) { tot += rs[i]; tot2 += rss[i]; }
    float mu   = tot * (1.0f / DD);
    float var  = tot2 * (1.0f / DD) - mu * mu;
    float rstd = rsqrtf(var + EPS);

    float4 g  = reinterpret_cast<const float4*>(gamma)[t];
    float4 be = reinterpret_cast<const float4*>(beta)[t];
    float4 o;
    o.x = (a.x - mu) * rstd * g.x + be.x;
    o.y = (a.y - mu) * rstd * g.y + be.y;
    o.z = (a.z - mu) * rstd * g.z + be.z;
    o.w = (a.w - mu) * rstd * g.w + be.w;
    reinterpret_cast<float4*>(y + (size_t)row * DD)[t] = o;
}

// ---------------------------------------------------------------------------
extern "C" void kernel_launch(void* const* d_in, const int* in_sizes, int n_in,
                              void* d_out, int out_size)
{
    const float*   q     = (const float*)d_in[0];
    const float*   k     = (const float*)d_in[1];
    const float*   v     = (const float*)d_in[2];
    const uint8_t* mask  = (const uint8_t*)d_in[3];
    const float*   wq    = (const float*)d_in[4];
    const float*   bq    = (const float*)d_in[5];
    const float*   wk    = (const float*)d_in[6];
    const float*   bk    = (const float*)d_in[7];
    const float*   wv    = (const float*)d_in[8];
    const float*   bv    = (const float*)d_in[9];
    const float*   wfc   = (const float*)d_in[10];
    const float*   bfc   = (const float*)d_in[11];
    const float*   gamma = (const float*)d_in[12];
    const float*   beta  = (const float*)d_in[13];

    float* out  = (float*)d_out;
    float* y    = out;
    float* attn = out + (size_t)BB * LL * DD;

    void *qhh, *qhl, *khh, *khl, *pvh, *pav, *ptmp;
    cudaGetSymbolAddress(&qhh, g_qh_hi);
    cudaGetSymbolAddress(&qhl, g_qh_lo);
    cudaGetSymbolAddress(&khh, g_kh_hi);
    cudaGetSymbolAddress(&khl, g_kh_lo);
    cudaGetSymbolAddress(&pvh, g_vh);
    cudaGetSymbolAddress(&pav, g_av);
    cudaGetSymbolAddress(&ptmp, g_tmp);

    const int G_SMEM = 2 * G_STAGE * 2;   // 75776 bytes
    const int S_SMEM = 4 * 9216 * 2;      // 73728 bytes
    cudaFuncSetAttribute(gemm_tc<0>, cudaFuncAttributeMaxDynamicSharedMemorySize, G_SMEM);
    cudaFuncSetAttribute(gemm_tc<1>, cudaFuncAttributeMaxDynamicSharedMemorySize, G_SMEM);
    cudaFuncSetAttribute(scores_tc, cudaFuncAttributeMaxDynamicSharedMemorySize, S_SMEM);

    dim3 gProj(DD / 128, ML / 128);          // (8, 32)
    gemm_tc<1><<<gProj, 256, G_SMEM>>>(q, wq, bq, nullptr,
        (__nv_bfloat16*)qhh, (__nv_bfloat16*)qhl, ML, DD, DD);
    gemm_tc<1><<<gProj, 256, G_SMEM>>>(k, wk, bk, nullptr,
        (__nv_bfloat16*)khh, (__nv_bfloat16*)khl, ML, DD, DD);
    gemm_tc<0><<<gProj, 256, G_SMEM>>>(v, wv, bv, (float*)pvh,
        nullptr, nullptr, ML, DD, DD);

    dim3 gScores(LL / 128, LL / 128, BB * HH);   // (8, 8, 64)
    scores_tc<<<gScores, 256, S_SMEM>>>(
        (const __nv_bfloat16*)qhh, (const __nv_bfloat16*)qhl,
        (const __nv_bfloat16*)khh, (const __nv_bfloat16*)khl, attn);

    softmax_rows<<<BB * HH * LL, 256>>>(attn, mask);

    dim3 gPV(LL / 128, 1, BB * HH);              // (8, 1, 64)
    attn_pv<<<gPV, 256>>>(attn, (const float*)pvh, (float*)pav);

    gemm_tc<0><<<gProj, 256, G_SMEM>>>((const float*)pav, wfc, bfc, (float*)ptmp,
        nullptr, nullptr, ML, DD, DD);

    add_layernorm<<<ML, 256>>>((const float*)ptmp, q, gamma, beta, y);
}